// round 7
// baseline (speedup 1.0000x reference)
#include <cuda_runtime.h>

// Fused 3-layer GraphConv, B=524288.
//   A_ENC:  agg[j]  = sum_{i=4j-3..4j+2} x[i mod 40]
//   A_PRED: agg2[j] = z1[j] + w*(z1[j-1] + z1[j+1]),  w = exp(-1/9)
//   A_DEC:  out[4k]=s[k], out[4k+1]=out[4k+2]=s[k]+s[k+1], out[4k+3]=s[k+1]
//           with s[j] = dot(relu(pred(z1)[j]), dec_rel_w)
//
// R6: 4 threads per element (sub0: nodes 0-2, sub1: 3-5, sub2: 6-7, sub3: 8-9).
// z1 shared through smem within the warp. Natural regs ~55 -> launch_bounds
// (128,8), 32 warps/SM, no spills (R2/R4/R5 all died to cap-induced spills).
// Weights read as broadcast LDS.128. y never staged: decoder streams y from
// gmem and writes out directly.

#define WPRED 0.8948393168143698f

__global__ void __launch_bounds__(128, 8)
fused_gnn_kernel(const float* __restrict__ x,
                 const float* __restrict__ z,
                 const float* __restrict__ y,
                 const float* __restrict__ enc_rel_w,
                 const float* __restrict__ enc_rel_b,
                 const float* __restrict__ enc_root_w,
                 const float* __restrict__ pred_rel_w,
                 const float* __restrict__ pred_rel_b,
                 const float* __restrict__ pred_root_w,
                 const float* __restrict__ dec_rel_w,
                 const float* __restrict__ dec_rel_b,
                 const float* __restrict__ dec_root_w,
                 float* __restrict__ out,
                 long long B)
{
    __shared__ __align__(16) float wER[64], wPR[64], wPO[64];   // [f*8+g]
    __shared__ float wErw[8], wErb[8], wPrb[8], wDrw[8];
    __shared__ float sDrb, sDrt;
    __shared__ __align__(16) float4 zb4[4][168];  // per warp: 8 el x 21 float4 (84 floats)
    __shared__ __align__(16) float4 xb4[4][88];   // per warp: 8 el x 11 float4 (44 floats)
    __shared__ float sS[4][96];                   // per warp: 8 el x 12 (s values)

    const int tid = threadIdx.x;
    if (tid < 64) {
        wER[tid] = enc_root_w[tid];
        wPR[tid] = pred_rel_w[tid];
        wPO[tid] = pred_root_w[tid];
    } else if (tid < 72) {
        int f = tid - 64;
        wErw[f] = enc_rel_w[f];
        wErb[f] = enc_rel_b[f];
        wPrb[f] = pred_rel_b[f];
        wDrw[f] = dec_rel_w[f];
    } else if (tid == 72) {
        sDrb = dec_rel_b[0]; sDrt = dec_root_w[0];
    }
    __syncthreads();

    const int warp = tid >> 5;
    const int lane = tid & 31;
    const int eloc = lane >> 2;   // element within warp (0..7)
    const int sub  = lane & 3;    // sub-thread within element
    const long long e0 = ((long long)blockIdx.x * 4 + warp) * 8;
    if (e0 >= B) return;
    const int nv = (B - e0 >= 8) ? 8 : (int)(B - e0);
    float4* xb = xb4[warp];
    float4* zb = zb4[warp];
    float*  ss = sS[warp];

    // ===== stage x: 8 elements x 10 float4, coalesced, rows padded to 11 f4 =====
    {
        const float4* xg = (const float4*)(x + e0 * 40);
        const int lim = nv * 10;
        #pragma unroll
        for (int k = 0; k < 3; k++) {
            int f4 = k * 32 + lane;
            if (f4 < lim) {
                float4 v = __ldcs(&xg[f4]);
                xb[(f4 / 10) * 11 + (f4 % 10)] = v;
            }
        }
    }
    // ===== stage z: 8 elements x 20 float4, coalesced, rows padded to 21 f4 =====
    {
        const float4* zg = (const float4*)(z + e0 * 80);
        const int lim = nv * 20;
        #pragma unroll
        for (int k = 0; k < 5; k++) {
            int f4 = k * 32 + lane;
            if (f4 < lim) {
                float4 v = __ldcs(&zg[f4]);
                zb[(f4 / 20) * 21 + (f4 % 20)] = v;
            }
        }
    }
    __syncwarp();

    const bool ev = (eloc < nv);
    const int jbeg = (sub < 2) ? sub * 3 : 6 + (sub - 2) * 2;  // {0,3,6,8}
    const int jcnt = (sub < 2) ? 3 : 2;

    // ===== encoder: each sub computes its nodes' z1, in place in smem =====
    if (ev) {
        #pragma unroll
        for (int i = 0; i < 3; i++) {
            if (i < jcnt) {
                const int j = jbeg + i;
                float4 vp = xb[eloc * 11 + ((j + 9) % 10)];
                float4 vc = xb[eloc * 11 + j];
                const float agg = (vp.y + vp.z) + (vp.w + vc.x) + (vc.y + vc.z);
                float4 a = zb[eloc * 21 + j * 2];
                float4 b = zb[eloc * 21 + j * 2 + 1];
                float zg8[8] = {a.x, a.y, a.z, a.w, b.x, b.y, b.z, b.w};
                float t[8];
                #pragma unroll
                for (int f = 0; f < 8; f++) {
                    float acc = fmaf(agg, wErw[f], wErb[f]);
                    float4 w0 = *(const float4*)&wER[f * 8];
                    float4 w1 = *(const float4*)&wER[f * 8 + 4];
                    acc = fmaf(zg8[0], w0.x, acc); acc = fmaf(zg8[1], w0.y, acc);
                    acc = fmaf(zg8[2], w0.z, acc); acc = fmaf(zg8[3], w0.w, acc);
                    acc = fmaf(zg8[4], w1.x, acc); acc = fmaf(zg8[5], w1.y, acc);
                    acc = fmaf(zg8[6], w1.z, acc); acc = fmaf(zg8[7], w1.w, acc);
                    t[f] = fmaxf(acc, 0.0f);
                }
                zb[eloc * 21 + j * 2]     = make_float4(t[0], t[1], t[2], t[3]);
                zb[eloc * 21 + j * 2 + 1] = make_float4(t[4], t[5], t[6], t[7]);
            }
        }
    }
    __syncwarp();   // all z1 rows visible to all subs

    // ===== predictor + dec_rel fold: s[j] into smem =====
    if (ev) {
        #pragma unroll
        for (int i = 0; i < 3; i++) {
            if (i < jcnt) {
                const int j = jbeg + i;
                const int jm = (j + 9) % 10, jp = (j + 1) % 10;
                float4 a = zb[eloc * 21 + jm * 2];
                float4 b = zb[eloc * 21 + jm * 2 + 1];
                float zm[8] = {a.x, a.y, a.z, a.w, b.x, b.y, b.z, b.w};
                a = zb[eloc * 21 + jp * 2];
                b = zb[eloc * 21 + jp * 2 + 1];
                float zn[8] = {a.x, a.y, a.z, a.w, b.x, b.y, b.z, b.w};
                a = zb[eloc * 21 + j * 2];
                b = zb[eloc * 21 + j * 2 + 1];
                float zc[8] = {a.x, a.y, a.z, a.w, b.x, b.y, b.z, b.w};
                float a2[8];
                #pragma unroll
                for (int g = 0; g < 8; g++)
                    a2[g] = fmaf(WPRED, zm[g] + zn[g], zc[g]);
                float sj = 0.0f;
                #pragma unroll
                for (int f = 0; f < 8; f++) {
                    float acc = wPrb[f];
                    float4 r0 = *(const float4*)&wPR[f * 8];
                    float4 r1 = *(const float4*)&wPR[f * 8 + 4];
                    acc = fmaf(a2[0], r0.x, acc); acc = fmaf(a2[1], r0.y, acc);
                    acc = fmaf(a2[2], r0.z, acc); acc = fmaf(a2[3], r0.w, acc);
                    acc = fmaf(a2[4], r1.x, acc); acc = fmaf(a2[5], r1.y, acc);
                    acc = fmaf(a2[6], r1.z, acc); acc = fmaf(a2[7], r1.w, acc);
                    float4 o0 = *(const float4*)&wPO[f * 8];
                    float4 o1 = *(const float4*)&wPO[f * 8 + 4];
                    acc = fmaf(zc[0], o0.x, acc); acc = fmaf(zc[1], o0.y, acc);
                    acc = fmaf(zc[2], o0.z, acc); acc = fmaf(zc[3], o0.w, acc);
                    acc = fmaf(zc[4], o1.x, acc); acc = fmaf(zc[5], o1.y, acc);
                    acc = fmaf(zc[6], o1.z, acc); acc = fmaf(zc[7], o1.w, acc);
                    sj = fmaf(fmaxf(acc, 0.0f), wDrw[f], sj);
                }
                ss[eloc * 12 + j] = sj;
            }
        }
    }
    __syncwarp();   // all s values visible

    // ===== decoder: y streamed from gmem, out written directly, coalesced =====
    {
        const float4* yg = (const float4*)(y + e0 * 40);
        float4* og = (float4*)(out + e0 * 40);
        const float drb = sDrb, drt = sDrt;
        const int lim = nv * 10;
        #pragma unroll
        for (int k = 0; k < 3; k++) {
            int f4 = k * 32 + lane;
            if (f4 < lim) {
                const int e = f4 / 10, c = f4 % 10;
                float4 v = __ldcs(&yg[f4]);
                const float s0 = ss[e * 12 + c];
                const float s1 = ss[e * 12 + ((c + 1) % 10)];
                const float c12 = s0 + s1;
                v.x = fmaf(v.x, drt, drb) + s0;
                v.y = fmaf(v.y, drt, drb) + c12;
                v.z = fmaf(v.z, drt, drb) + c12;
                v.w = fmaf(v.w, drt, drb) + s1;
                __stcs(&og[f4], v);
            }
        }
    }
}

extern "C" void kernel_launch(void* const* d_in, const int* in_sizes, int n_in,
                              void* d_out, int out_size)
{
    const float* x          = (const float*)d_in[0];
    const float* z          = (const float*)d_in[1];
    const float* y          = (const float*)d_in[2];
    const float* enc_rel_w  = (const float*)d_in[3];
    const float* enc_rel_b  = (const float*)d_in[4];
    const float* enc_root_w = (const float*)d_in[5];
    const float* pred_rel_w = (const float*)d_in[6];
    const float* pred_rel_b = (const float*)d_in[7];
    const float* pred_root_w= (const float*)d_in[8];
    const float* dec_rel_w  = (const float*)d_in[9];
    const float* dec_rel_b  = (const float*)d_in[10];
    const float* dec_root_w = (const float*)d_in[11];

    const long long B = (long long)in_sizes[0] / 40;
    const int threads = 128;                      // 4 warps x 8 elements x 4 subs
    const long long elems_per_block = 32;
    const int blocks = (int)((B + elems_per_block - 1) / elems_per_block);

    fused_gnn_kernel<<<blocks, threads>>>(
        x, z, y, enc_rel_w, enc_rel_b, enc_root_w,
        pred_rel_w, pred_rel_b, pred_root_w,
        dec_rel_w, dec_rel_b, dec_root_w,
        (float*)d_out, B);
}

// round 8
// speedup vs baseline: 2.1149x; 2.1149x over previous
#include <cuda_runtime.h>

// Fused 3-layer GraphConv, B=524288.
//   A_ENC:  agg[j]  = sum_{i=4j-3..4j+2} x[i mod 40]
//   A_PRED: agg2[j] = z1[j] + w*(z1[j-1] + z1[j+1]),  w = exp(-1/9)
//   A_DEC:  out[4k]=s[k], out[4k+1]=out[4k+2]=s[k]+s[k+1], out[4k+3]=s[k+1]
//           with s[j] = dot(relu(pred(z1)[j]), dec_rel_w)
//
// R7: R3 structure (best: 177us) + anti-hoist volatile LDS.128 for all weight
// and z1 reads (ptxas weight-hoisting across the unrolled node loop was the
// hidden +60 reg term that caused every capped build to spill). s[] lands in
// a small padded smem array so the decoder streams y/out directly (no y
// staging passes). launch_bounds(128,4), ~50KB smem -> 4 blocks/SM.

#define WPRED 0.8948393168143698f

// Anti-hoist shared loads: asm volatile cannot be CSE'd/hoisted/batched.
__device__ __forceinline__ float4 lds128a(unsigned a) {
    float4 r;
    asm volatile("ld.shared.v4.f32 {%0,%1,%2,%3}, [%4];"
                 : "=f"(r.x), "=f"(r.y), "=f"(r.z), "=f"(r.w) : "r"(a));
    return r;
}
__device__ __forceinline__ unsigned saddr(const void* p) {
    return (unsigned)__cvta_generic_to_shared(p);
}

__global__ void __launch_bounds__(128, 4)
fused_gnn_kernel(const float* __restrict__ x,
                 const float* __restrict__ z,
                 const float* __restrict__ y,
                 const float* __restrict__ enc_rel_w,
                 const float* __restrict__ enc_rel_b,
                 const float* __restrict__ enc_root_w,
                 const float* __restrict__ pred_rel_w,
                 const float* __restrict__ pred_rel_b,
                 const float* __restrict__ pred_root_w,
                 const float* __restrict__ dec_rel_w,
                 const float* __restrict__ dec_rel_b,
                 const float* __restrict__ dec_root_w,
                 float* __restrict__ out,
                 long long B)
{
    __shared__ __align__(16) float wER[64], wPR[64], wPO[64];   // [f*8+g]
    __shared__ __align__(16) float4 wSm[8];   // {enc_rel_w, enc_rel_b, pred_rel_b, dec_rel_w}[f]
    __shared__ float sDrb, sDrt;
    __shared__ __align__(16) float4 sbuf4[4][672];  // per warp: 32 rows x 84 floats
    __shared__ float sS[4][352];                    // per warp: 32 el x 11 (pad 11, gcd(11,32)=1)

    const int tid = threadIdx.x;
    if (tid < 64) {
        wER[tid] = enc_root_w[tid];
        wPR[tid] = pred_rel_w[tid];
        wPO[tid] = pred_root_w[tid];
    } else if (tid < 72) {
        int f = tid - 64;
        wSm[f] = make_float4(enc_rel_w[f], enc_rel_b[f], pred_rel_b[f], dec_rel_w[f]);
    } else if (tid == 72) {
        sDrb = dec_rel_b[0]; sDrt = dec_root_w[0];
    }
    __syncthreads();

    const int warp = tid >> 5;
    const int lane = tid & 31;
    const long long e0 = ((long long)blockIdx.x * 4 + warp) * 32;
    if (e0 >= B) return;
    const int nv = (B - e0 >= 32) ? 32 : (int)(B - e0);
    float* buf = (float*)sbuf4[warp];
    float* ss  = sS[warp];

    const unsigned wER_a = saddr(wER);
    const unsigned wPR_a = saddr(wPR);
    const unsigned wPO_a = saddr(wPO);
    const unsigned wSm_a = saddr(wSm);

    // ===== stage x (coalesced, streaming), rows padded to 44 floats =====
    {
        const float4* xg = (const float4*)(x + e0 * 40);
        const int lim = nv * 10;
        #pragma unroll
        for (int k = 0; k < 10; k++) {
            int f4 = k * 32 + lane;
            if (f4 < lim) {
                float4 v = __ldcs(&xg[f4]);
                *(float4*)&buf[(f4 / 10) * 44 + (f4 % 10) * 4] = v;
            }
        }
    }
    __syncwarp();

    // agg[j] = (last 3 of float4[j-1]) + (first 3 of float4[j]), rolling window
    float agg[10];
    if (lane < nv) {
        const unsigned mx = saddr(&buf[lane * 44]);
        float4 vp = lds128a(mx + 9 * 16);
        #pragma unroll
        for (int j = 0; j < 10; j++) {
            float4 v = lds128a(mx + j * 16);
            agg[j] = (vp.y + vp.z) + (vp.w + v.x) + (v.y + v.z);
            vp = v;
        }
    }
    __syncwarp();

    // ===== stage z (coalesced, streaming), rows padded to 84 floats =====
    {
        const float4* zg = (const float4*)(z + e0 * 80);
        const int lim = nv * 20;
        #pragma unroll
        for (int k = 0; k < 20; k++) {
            int f4 = k * 32 + lane;
            if (f4 < lim) {
                float4 v = __ldcs(&zg[f4]);
                *(float4*)&buf[(f4 / 20) * 84 + (f4 % 20) * 4] = v;
            }
        }
    }
    __syncwarp();

    if (lane < nv) {
        float* zrow = &buf[lane * 84];
        const unsigned zr_a = saddr(zrow);

        // ---- encoder: z1[j] overwrites z[j] in smem (thread-private row) ----
        #pragma unroll
        for (int j = 0; j < 10; j++) {
            float4 a = lds128a(zr_a + j * 32);
            float4 b = lds128a(zr_a + j * 32 + 16);
            float t[8];
            #pragma unroll
            for (int f = 0; f < 8; f++) {
                float4 ws = lds128a(wSm_a + f * 16);
                float4 w0 = lds128a(wER_a + f * 32);
                float4 w1 = lds128a(wER_a + f * 32 + 16);
                float acc = fmaf(agg[j], ws.x, ws.y);
                acc = fmaf(a.x, w0.x, acc); acc = fmaf(a.y, w0.y, acc);
                acc = fmaf(a.z, w0.z, acc); acc = fmaf(a.w, w0.w, acc);
                acc = fmaf(b.x, w1.x, acc); acc = fmaf(b.y, w1.y, acc);
                acc = fmaf(b.z, w1.z, acc); acc = fmaf(b.w, w1.w, acc);
                t[f] = fmaxf(acc, 0.0f);
            }
            *(float4*)&zrow[j * 8]     = make_float4(t[0], t[1], t[2], t[3]);
            *(float4*)&zrow[j * 8 + 4] = make_float4(t[4], t[5], t[6], t[7]);
        }

        // ---- predictor + dec_rel fold: all z1 in smem, no wrap special case ----
        #pragma unroll
        for (int j = 0; j < 10; j++) {
            const int jm = (j + 9) % 10, jp = (j + 1) % 10;
            float4 ma = lds128a(zr_a + jm * 32);
            float4 mb = lds128a(zr_a + jm * 32 + 16);
            float4 na = lds128a(zr_a + jp * 32);
            float4 nb = lds128a(zr_a + jp * 32 + 16);
            float4 ca = lds128a(zr_a + j * 32);
            float4 cb = lds128a(zr_a + j * 32 + 16);
            float4 Aa, Ab;   // a2 = WPRED*(zm+zn) + zc
            Aa.x = fmaf(WPRED, ma.x + na.x, ca.x);
            Aa.y = fmaf(WPRED, ma.y + na.y, ca.y);
            Aa.z = fmaf(WPRED, ma.z + na.z, ca.z);
            Aa.w = fmaf(WPRED, ma.w + na.w, ca.w);
            Ab.x = fmaf(WPRED, mb.x + nb.x, cb.x);
            Ab.y = fmaf(WPRED, mb.y + nb.y, cb.y);
            Ab.z = fmaf(WPRED, mb.z + nb.z, cb.z);
            Ab.w = fmaf(WPRED, mb.w + nb.w, cb.w);
            float sj = 0.0f;
            #pragma unroll
            for (int f = 0; f < 8; f++) {
                float4 ws = lds128a(wSm_a + f * 16);
                float4 r0 = lds128a(wPR_a + f * 32);
                float4 r1 = lds128a(wPR_a + f * 32 + 16);
                float4 o0 = lds128a(wPO_a + f * 32);
                float4 o1 = lds128a(wPO_a + f * 32 + 16);
                float acc = ws.z;   // pred_rel_b[f]
                acc = fmaf(Aa.x, r0.x, acc); acc = fmaf(Aa.y, r0.y, acc);
                acc = fmaf(Aa.z, r0.z, acc); acc = fmaf(Aa.w, r0.w, acc);
                acc = fmaf(Ab.x, r1.x, acc); acc = fmaf(Ab.y, r1.y, acc);
                acc = fmaf(Ab.z, r1.z, acc); acc = fmaf(Ab.w, r1.w, acc);
                acc = fmaf(ca.x, o0.x, acc); acc = fmaf(ca.y, o0.y, acc);
                acc = fmaf(ca.z, o0.z, acc); acc = fmaf(ca.w, o0.w, acc);
                acc = fmaf(cb.x, o1.x, acc); acc = fmaf(cb.y, o1.y, acc);
                acc = fmaf(cb.z, o1.z, acc); acc = fmaf(cb.w, o1.w, acc);
                sj = fmaf(fmaxf(acc, 0.0f), ws.w, sj);   // * dec_rel_w[f]
            }
            ss[lane * 11 + j] = sj;
        }
    }
    __syncwarp();   // s values visible warp-wide

    // ===== decoder: y streamed from gmem, out written directly, coalesced =====
    {
        const float4* yg = (const float4*)(y + e0 * 40);
        float4* og = (float4*)(out + e0 * 40);
        const float drb = sDrb, drt = sDrt;
        const int lim = nv * 10;
        #pragma unroll
        for (int k = 0; k < 10; k++) {
            int f4 = k * 32 + lane;
            if (f4 < lim) {
                const int e = f4 / 10, c = f4 % 10;
                float4 v = __ldcs(&yg[f4]);
                const float s0 = ss[e * 11 + c];
                const float s1 = ss[e * 11 + ((c + 1) % 10)];
                const float c12 = s0 + s1;
                v.x = fmaf(v.x, drt, drb) + s0;
                v.y = fmaf(v.y, drt, drb) + c12;
                v.z = fmaf(v.z, drt, drb) + c12;
                v.w = fmaf(v.w, drt, drb) + s1;
                __stcs(&og[f4], v);
            }
        }
    }
}

extern "C" void kernel_launch(void* const* d_in, const int* in_sizes, int n_in,
                              void* d_out, int out_size)
{
    const float* x          = (const float*)d_in[0];
    const float* z          = (const float*)d_in[1];
    const float* y          = (const float*)d_in[2];
    const float* enc_rel_w  = (const float*)d_in[3];
    const float* enc_rel_b  = (const float*)d_in[4];
    const float* enc_root_w = (const float*)d_in[5];
    const float* pred_rel_w = (const float*)d_in[6];
    const float* pred_rel_b = (const float*)d_in[7];
    const float* pred_root_w= (const float*)d_in[8];
    const float* dec_rel_w  = (const float*)d_in[9];
    const float* dec_rel_b  = (const float*)d_in[10];
    const float* dec_root_w = (const float*)d_in[11];

    const long long B = (long long)in_sizes[0] / 40;
    const int threads = 128;                      // 4 warps x 32 elements
    const long long elems_per_block = 128;
    const int blocks = (int)((B + elems_per_block - 1) / elems_per_block);

    fused_gnn_kernel<<<blocks, threads>>>(
        x, z, y, enc_rel_w, enc_rel_b, enc_root_w,
        pred_rel_w, pred_rel_b, pred_root_w,
        dec_rel_w, dec_rel_b, dec_root_w,
        (float*)d_out, B);
}

// round 9
// speedup vs baseline: 2.1359x; 1.0099x over previous
#include <cuda_runtime.h>

// Fused 3-layer GraphConv, B=524288.
//   A_ENC:  agg[j]  = sum_{i=4j-3..4j+2} x[i mod 40]
//   A_PRED: agg2[j] = z1[j] + w*(z1[j-1] + z1[j+1]),  w = exp(-1/9)
//   A_DEC:  out[4k]=s[k], out[4k+1]=out[4k+2]=s[k]+s[k+1], out[4k+3]=s[k+1]
//           with s[j] = dot(relu(pred(z1)[j]), dec_rel_w)
//
// R8 vs R7 (211us, no spills but dependency-latency bound):
//  - explicit rolling 3-row z1 register window (1 row LDS per node, not 3)
//  - split accumulator chains: 4 independent partials per f (crit path 68->25)
//  - z1 stores volatile (blocks store->load forwarding reg blowup), weight
//    loads volatile (blocks hoisting) -- the R7 spill fix is preserved

#define WPRED 0.8948393168143698f

__device__ __forceinline__ float4 lds128a(unsigned a) {
    float4 r;
    asm volatile("ld.shared.v4.f32 {%0,%1,%2,%3}, [%4];"
                 : "=f"(r.x), "=f"(r.y), "=f"(r.z), "=f"(r.w) : "r"(a));
    return r;
}
__device__ __forceinline__ void sts128a(unsigned a, float4 v) {
    asm volatile("st.shared.v4.f32 [%0], {%1,%2,%3,%4};"
                 :: "r"(a), "f"(v.x), "f"(v.y), "f"(v.z), "f"(v.w));
}
__device__ __forceinline__ unsigned saddr(const void* p) {
    return (unsigned)__cvta_generic_to_shared(p);
}

// predictor node + dec_rel fold, split accumulator chains
__device__ __forceinline__ float pred_s(float4 ma, float4 mb, float4 ca, float4 cb,
                                        float4 na, float4 nb,
                                        unsigned wPR_a, unsigned wPO_a, unsigned wSm_a)
{
    float4 Aa, Ab;
    Aa.x = fmaf(WPRED, ma.x + na.x, ca.x);
    Aa.y = fmaf(WPRED, ma.y + na.y, ca.y);
    Aa.z = fmaf(WPRED, ma.z + na.z, ca.z);
    Aa.w = fmaf(WPRED, ma.w + na.w, ca.w);
    Ab.x = fmaf(WPRED, mb.x + nb.x, cb.x);
    Ab.y = fmaf(WPRED, mb.y + nb.y, cb.y);
    Ab.z = fmaf(WPRED, mb.z + nb.z, cb.z);
    Ab.w = fmaf(WPRED, mb.w + nb.w, cb.w);
    float sj0 = 0.0f, sj1 = 0.0f;
    #pragma unroll
    for (int f = 0; f < 8; f++) {
        float4 ws = lds128a(wSm_a + f * 16);
        float4 r0 = lds128a(wPR_a + f * 32);
        float4 r1 = lds128a(wPR_a + f * 32 + 16);
        float4 o0 = lds128a(wPO_a + f * 32);
        float4 o1 = lds128a(wPO_a + f * 32 + 16);
        float p0 = fmaf(Aa.x, r0.x, fmaf(Aa.y, r0.y, fmaf(Aa.z, r0.z, fmaf(Aa.w, r0.w, ws.z))));
        float p1 = fmaf(Ab.x, r1.x, fmaf(Ab.y, r1.y, fmaf(Ab.z, r1.z, Ab.w * r1.w)));
        float p2 = fmaf(ca.x, o0.x, fmaf(ca.y, o0.y, fmaf(ca.z, o0.z, ca.w * o0.w)));
        float p3 = fmaf(cb.x, o1.x, fmaf(cb.y, o1.y, fmaf(cb.z, o1.z, cb.w * o1.w)));
        float acc = (p0 + p1) + (p2 + p3);
        float r = fmaxf(acc, 0.0f);
        if (f & 1) sj1 = fmaf(r, ws.w, sj1);
        else       sj0 = fmaf(r, ws.w, sj0);
    }
    return sj0 + sj1;
}

__global__ void __launch_bounds__(128, 4)
fused_gnn_kernel(const float* __restrict__ x,
                 const float* __restrict__ z,
                 const float* __restrict__ y,
                 const float* __restrict__ enc_rel_w,
                 const float* __restrict__ enc_rel_b,
                 const float* __restrict__ enc_root_w,
                 const float* __restrict__ pred_rel_w,
                 const float* __restrict__ pred_rel_b,
                 const float* __restrict__ pred_root_w,
                 const float* __restrict__ dec_rel_w,
                 const float* __restrict__ dec_rel_b,
                 const float* __restrict__ dec_root_w,
                 float* __restrict__ out,
                 long long B)
{
    __shared__ __align__(16) float wER[64], wPR[64], wPO[64];   // [f*8+g]
    __shared__ __align__(16) float4 wSm[8];   // {enc_rel_w, enc_rel_b, pred_rel_b, dec_rel_w}[f]
    __shared__ float sDrb, sDrt;
    __shared__ __align__(16) float4 sbuf4[4][672];  // per warp: 32 rows x 84 floats
    __shared__ float sS[4][352];                    // per warp: 32 el x stride 11

    const int tid = threadIdx.x;
    if (tid < 64) {
        wER[tid] = enc_root_w[tid];
        wPR[tid] = pred_rel_w[tid];
        wPO[tid] = pred_root_w[tid];
    } else if (tid < 72) {
        int f = tid - 64;
        wSm[f] = make_float4(enc_rel_w[f], enc_rel_b[f], pred_rel_b[f], dec_rel_w[f]);
    } else if (tid == 72) {
        sDrb = dec_rel_b[0]; sDrt = dec_root_w[0];
    }
    __syncthreads();

    const int warp = tid >> 5;
    const int lane = tid & 31;
    const long long e0 = ((long long)blockIdx.x * 4 + warp) * 32;
    if (e0 >= B) return;
    const int nv = (B - e0 >= 32) ? 32 : (int)(B - e0);
    float* buf = (float*)sbuf4[warp];
    float* ss  = sS[warp];

    const unsigned wER_a = saddr(wER);
    const unsigned wPR_a = saddr(wPR);
    const unsigned wPO_a = saddr(wPO);
    const unsigned wSm_a = saddr(wSm);

    // ===== stage x (coalesced, streaming), rows padded to 44 floats =====
    {
        const float4* xg = (const float4*)(x + e0 * 40);
        const int lim = nv * 10;
        #pragma unroll
        for (int k = 0; k < 10; k++) {
            int f4 = k * 32 + lane;
            if (f4 < lim) {
                float4 v = __ldcs(&xg[f4]);
                *(float4*)&buf[(f4 / 10) * 44 + (f4 % 10) * 4] = v;
            }
        }
    }
    __syncwarp();

    // agg[j] = (last 3 of float4[j-1]) + (first 3 of float4[j]), rolling window
    float agg[10];
    if (lane < nv) {
        const unsigned mx = saddr(&buf[lane * 44]);
        float4 vp = lds128a(mx + 9 * 16);
        #pragma unroll
        for (int j = 0; j < 10; j++) {
            float4 v = lds128a(mx + j * 16);
            agg[j] = (vp.y + vp.z) + (vp.w + v.x) + (v.y + v.z);
            vp = v;
        }
    }
    __syncwarp();

    // ===== stage z (coalesced, streaming), rows padded to 84 floats =====
    {
        const float4* zg = (const float4*)(z + e0 * 80);
        const int lim = nv * 20;
        #pragma unroll
        for (int k = 0; k < 20; k++) {
            int f4 = k * 32 + lane;
            if (f4 < lim) {
                float4 v = __ldcs(&zg[f4]);
                *(float4*)&buf[(f4 / 20) * 84 + (f4 % 20) * 4] = v;
            }
        }
    }
    __syncwarp();

    if (lane < nv) {
        const unsigned zr_a = saddr(&buf[lane * 84]);

        // ---- encoder: z1[j] overwrites z[j] in smem, split chains ----
        #pragma unroll
        for (int j = 0; j < 10; j++) {
            float4 a = lds128a(zr_a + j * 32);
            float4 b = lds128a(zr_a + j * 32 + 16);
            float t[8];
            #pragma unroll
            for (int f = 0; f < 8; f++) {
                float4 ws = lds128a(wSm_a + f * 16);
                float4 w0 = lds128a(wER_a + f * 32);
                float4 w1 = lds128a(wER_a + f * 32 + 16);
                float c0 = fmaf(a.x, w0.x, fmaf(a.y, w0.y,
                           fmaf(a.z, w0.z, fmaf(a.w, w0.w, fmaf(agg[j], ws.x, ws.y)))));
                float c1 = fmaf(b.x, w1.x, fmaf(b.y, w1.y, fmaf(b.z, w1.z, b.w * w1.w)));
                t[f] = fmaxf(c0 + c1, 0.0f);
            }
            sts128a(zr_a + j * 32,      make_float4(t[0], t[1], t[2], t[3]));
            sts128a(zr_a + j * 32 + 16, make_float4(t[4], t[5], t[6], t[7]));
        }

        // ---- predictor: explicit rolling window, 1 row load per node ----
        float4 maA = lds128a(zr_a + 0);        // z1[0]
        float4 maB = lds128a(zr_a + 16);
        float4 caA = lds128a(zr_a + 32);       // z1[1]
        float4 caB = lds128a(zr_a + 48);
        #pragma unroll
        for (int j = 1; j <= 8; j++) {
            float4 naA = lds128a(zr_a + (j + 1) * 32);
            float4 naB = lds128a(zr_a + (j + 1) * 32 + 16);
            ss[lane * 11 + j] = pred_s(maA, maB, caA, caB, naA, naB, wPR_a, wPO_a, wSm_a);
            maA = caA; maB = caB; caA = naA; caB = naB;
        }
        // window: ma=z1[8], ca=z1[9]
        float4 naA = lds128a(zr_a + 0);        // z1[0]
        float4 naB = lds128a(zr_a + 16);
        ss[lane * 11 + 9] = pred_s(maA, maB, caA, caB, naA, naB, wPR_a, wPO_a, wSm_a);
        maA = caA; maB = caB; caA = naA; caB = naB;   // ma=z1[9], ca=z1[0]
        naA = lds128a(zr_a + 32);              // z1[1]
        naB = lds128a(zr_a + 48);
        ss[lane * 11 + 0] = pred_s(maA, maB, caA, caB, naA, naB, wPR_a, wPO_a, wSm_a);
    }
    __syncwarp();   // s values visible warp-wide

    // ===== decoder: y streamed from gmem, out written directly, coalesced =====
    {
        const float4* yg = (const float4*)(y + e0 * 40);
        float4* og = (float4*)(out + e0 * 40);
        const float drb = sDrb, drt = sDrt;
        const int lim = nv * 10;
        #pragma unroll
        for (int k = 0; k < 10; k++) {
            int f4 = k * 32 + lane;
            if (f4 < lim) {
                const int e = f4 / 10, c = f4 % 10;
                float4 v = __ldcs(&yg[f4]);
                const float s0 = ss[e * 11 + c];
                const float s1 = ss[e * 11 + ((c + 1) % 10)];
                const float c12 = s0 + s1;
                v.x = fmaf(v.x, drt, drb) + s0;
                v.y = fmaf(v.y, drt, drb) + c12;
                v.z = fmaf(v.z, drt, drb) + c12;
                v.w = fmaf(v.w, drt, drb) + s1;
                __stcs(&og[f4], v);
            }
        }
    }
}

extern "C" void kernel_launch(void* const* d_in, const int* in_sizes, int n_in,
                              void* d_out, int out_size)
{
    const float* x          = (const float*)d_in[0];
    const float* z          = (const float*)d_in[1];
    const float* y          = (const float*)d_in[2];
    const float* enc_rel_w  = (const float*)d_in[3];
    const float* enc_rel_b  = (const float*)d_in[4];
    const float* enc_root_w = (const float*)d_in[5];
    const float* pred_rel_w = (const float*)d_in[6];
    const float* pred_rel_b = (const float*)d_in[7];
    const float* pred_root_w= (const float*)d_in[8];
    const float* dec_rel_w  = (const float*)d_in[9];
    const float* dec_rel_b  = (const float*)d_in[10];
    const float* dec_root_w = (const float*)d_in[11];

    const long long B = (long long)in_sizes[0] / 40;
    const int threads = 128;                      // 4 warps x 32 elements
    const long long elems_per_block = 128;
    const int blocks = (int)((B + elems_per_block - 1) / elems_per_block);

    fused_gnn_kernel<<<blocks, threads>>>(
        x, z, y, enc_rel_w, enc_rel_b, enc_root_w,
        pred_rel_w, pred_rel_b, pred_root_w,
        dec_rel_w, dec_rel_b, dec_root_w,
        (float*)d_out, B);
}

// round 10
// speedup vs baseline: 2.4161x; 1.1312x over previous
#include <cuda_runtime.h>

// Fused 3-layer GraphConv, B=524288.
//   A_ENC:  agg[j]  = sum_{i=4j-3..4j+2} x[i mod 40]
//   A_PRED: agg2[j] = z1[j] + w*(z1[j-1] + z1[j+1]),  w = exp(-1/9)
//   A_DEC:  out[4k]=s[k], out[4k+1]=out[4k+2]=s[k]+s[k+1], out[4k+3]=s[k+1]
//           with s[j] = dot(relu(pred(z1)[j]), dec_rel_w)
//
// R9 vs R8 (209us, ~640 weight-LDS per thread = serialized crossbar stream):
//  - weights in __constant__ (populated via cudaMemcpyToSymbolAsync, D2D,
//    graph-capturable). Warp-uniform -> LDCU/UR operands: zero regular regs,
//    zero smem crossbar cost for weights.
//  - s[10] kept in regs, then written to an alias of the dead z1 smem region:
//    smem/block 43.1KB -> 5 blocks/SM, launch_bounds(128,5), 20 warps/SM.
//  - z1 rows keep volatile LDS/STS (anti store->load-forwarding reg blowup).

#define WPRED 0.8948393168143698f

__constant__ float cER[64];   // enc_root_w  [f*8+g]
__constant__ float cPR[64];   // pred_rel_w
__constant__ float cPO[64];   // pred_root_w
__constant__ float cErw[8], cErb[8], cPrb[8], cDrw[8];
__constant__ float cDrb[1], cDrt[1];

__device__ __forceinline__ float4 lds128a(unsigned a) {
    float4 r;
    asm volatile("ld.shared.v4.f32 {%0,%1,%2,%3}, [%4];"
                 : "=f"(r.x), "=f"(r.y), "=f"(r.z), "=f"(r.w) : "r"(a));
    return r;
}
__device__ __forceinline__ void sts128a(unsigned a, float4 v) {
    asm volatile("st.shared.v4.f32 [%0], {%1,%2,%3,%4};"
                 :: "r"(a), "f"(v.x), "f"(v.y), "f"(v.z), "f"(v.w));
}
__device__ __forceinline__ unsigned saddr(const void* p) {
    return (unsigned)__cvta_generic_to_shared(p);
}

// predictor node + dec_rel fold, split accumulator chains, constant weights
__device__ __forceinline__ float pred_s(float4 ma, float4 mb, float4 ca, float4 cb,
                                        float4 na, float4 nb)
{
    float4 Aa, Ab;
    Aa.x = fmaf(WPRED, ma.x + na.x, ca.x);
    Aa.y = fmaf(WPRED, ma.y + na.y, ca.y);
    Aa.z = fmaf(WPRED, ma.z + na.z, ca.z);
    Aa.w = fmaf(WPRED, ma.w + na.w, ca.w);
    Ab.x = fmaf(WPRED, mb.x + nb.x, cb.x);
    Ab.y = fmaf(WPRED, mb.y + nb.y, cb.y);
    Ab.z = fmaf(WPRED, mb.z + nb.z, cb.z);
    Ab.w = fmaf(WPRED, mb.w + nb.w, cb.w);
    const float4* pr4 = (const float4*)cPR;
    const float4* po4 = (const float4*)cPO;
    float sj0 = 0.0f, sj1 = 0.0f;
    #pragma unroll
    for (int f = 0; f < 8; f++) {
        float4 r0 = pr4[f * 2], r1 = pr4[f * 2 + 1];
        float4 o0 = po4[f * 2], o1 = po4[f * 2 + 1];
        float p0 = fmaf(Aa.x, r0.x, fmaf(Aa.y, r0.y, fmaf(Aa.z, r0.z, fmaf(Aa.w, r0.w, cPrb[f]))));
        float p1 = fmaf(Ab.x, r1.x, fmaf(Ab.y, r1.y, fmaf(Ab.z, r1.z, Ab.w * r1.w)));
        float p2 = fmaf(ca.x, o0.x, fmaf(ca.y, o0.y, fmaf(ca.z, o0.z, ca.w * o0.w)));
        float p3 = fmaf(cb.x, o1.x, fmaf(cb.y, o1.y, fmaf(cb.z, o1.z, cb.w * o1.w)));
        float r = fmaxf((p0 + p1) + (p2 + p3), 0.0f);
        if (f & 1) sj1 = fmaf(r, cDrw[f], sj1);
        else       sj0 = fmaf(r, cDrw[f], sj0);
    }
    return sj0 + sj1;
}

__global__ void __launch_bounds__(128, 5)
fused_gnn_kernel(const float* __restrict__ x,
                 const float* __restrict__ z,
                 const float* __restrict__ y,
                 float* __restrict__ out,
                 long long B)
{
    __shared__ __align__(16) float4 sbuf4[4][672];  // per warp: 32 rows x 84 floats

    const int tid = threadIdx.x;
    const int warp = tid >> 5;
    const int lane = tid & 31;
    const long long e0 = ((long long)blockIdx.x * 4 + warp) * 32;
    if (e0 >= B) return;
    const int nv = (B - e0 >= 32) ? 32 : (int)(B - e0);
    float* buf = (float*)sbuf4[warp];
    float* ss  = buf;                 // alias: reused after z1 is dead (32 x 11 floats)

    // ===== stage x (coalesced, streaming), rows padded to 44 floats =====
    {
        const float4* xg = (const float4*)(x + e0 * 40);
        const int lim = nv * 10;
        #pragma unroll
        for (int k = 0; k < 10; k++) {
            int f4 = k * 32 + lane;
            if (f4 < lim) {
                float4 v = __ldcs(&xg[f4]);
                *(float4*)&buf[(f4 / 10) * 44 + (f4 % 10) * 4] = v;
            }
        }
    }
    __syncwarp();

    // agg[j] = (last 3 of float4[j-1]) + (first 3 of float4[j]), rolling window
    float agg[10];
    if (lane < nv) {
        const unsigned mx = saddr(&buf[lane * 44]);
        float4 vp = lds128a(mx + 9 * 16);
        #pragma unroll
        for (int j = 0; j < 10; j++) {
            float4 v = lds128a(mx + j * 16);
            agg[j] = (vp.y + vp.z) + (vp.w + v.x) + (v.y + v.z);
            vp = v;
        }
    }
    __syncwarp();

    // ===== stage z (coalesced, streaming), rows padded to 84 floats =====
    {
        const float4* zg = (const float4*)(z + e0 * 80);
        const int lim = nv * 20;
        #pragma unroll
        for (int k = 0; k < 20; k++) {
            int f4 = k * 32 + lane;
            if (f4 < lim) {
                float4 v = __ldcs(&zg[f4]);
                *(float4*)&buf[(f4 / 20) * 84 + (f4 % 20) * 4] = v;
            }
        }
    }
    __syncwarp();

    float s[10];
    if (lane < nv) {
        const unsigned zr_a = saddr(&buf[lane * 84]);
        const float4* er4 = (const float4*)cER;

        // ---- encoder: z1[j] overwrites z[j] in smem, split chains ----
        #pragma unroll
        for (int j = 0; j < 10; j++) {
            float4 a = lds128a(zr_a + j * 32);
            float4 b = lds128a(zr_a + j * 32 + 16);
            float t[8];
            #pragma unroll
            for (int f = 0; f < 8; f++) {
                float4 w0 = er4[f * 2], w1 = er4[f * 2 + 1];
                float c0 = fmaf(a.x, w0.x, fmaf(a.y, w0.y,
                           fmaf(a.z, w0.z, fmaf(a.w, w0.w, fmaf(agg[j], cErw[f], cErb[f])))));
                float c1 = fmaf(b.x, w1.x, fmaf(b.y, w1.y, fmaf(b.z, w1.z, b.w * w1.w)));
                t[f] = fmaxf(c0 + c1, 0.0f);
            }
            sts128a(zr_a + j * 32,      make_float4(t[0], t[1], t[2], t[3]));
            sts128a(zr_a + j * 32 + 16, make_float4(t[4], t[5], t[6], t[7]));
        }

        // ---- predictor: explicit rolling window, 1 row load per node ----
        float4 maA = lds128a(zr_a + 0);        // z1[0]
        float4 maB = lds128a(zr_a + 16);
        float4 caA = lds128a(zr_a + 32);       // z1[1]
        float4 caB = lds128a(zr_a + 48);
        #pragma unroll
        for (int j = 1; j <= 8; j++) {
            float4 naA = lds128a(zr_a + (j + 1) * 32);
            float4 naB = lds128a(zr_a + (j + 1) * 32 + 16);
            s[j] = pred_s(maA, maB, caA, caB, naA, naB);
            maA = caA; maB = caB; caA = naA; caB = naB;
        }
        // window: ma=z1[8], ca=z1[9]
        float4 naA = lds128a(zr_a + 0);        // z1[0]
        float4 naB = lds128a(zr_a + 16);
        s[9] = pred_s(maA, maB, caA, caB, naA, naB);
        maA = caA; maB = caB; caA = naA; caB = naB;   // ma=z1[9], ca=z1[0]
        naA = lds128a(zr_a + 32);              // z1[1]
        naB = lds128a(zr_a + 48);
        s[0] = pred_s(maA, maB, caA, caB, naA, naB);
    }
    __syncwarp();   // all pred reads of z1 done -> safe to overwrite via alias

    if (lane < nv) {
        #pragma unroll
        for (int j = 0; j < 10; j++)
            ss[lane * 11 + j] = s[j];
    }
    __syncwarp();

    // ===== decoder: y streamed from gmem, out written directly, coalesced =====
    {
        const float4* yg = (const float4*)(y + e0 * 40);
        float4* og = (float4*)(out + e0 * 40);
        const float drb = cDrb[0], drt = cDrt[0];
        const int lim = nv * 10;
        #pragma unroll
        for (int k = 0; k < 10; k++) {
            int f4 = k * 32 + lane;
            if (f4 < lim) {
                const int e = f4 / 10, c = f4 % 10;
                float4 v = __ldcs(&yg[f4]);
                const float s0 = ss[e * 11 + c];
                const float s1 = ss[e * 11 + ((c + 1) % 10)];
                const float c12 = s0 + s1;
                v.x = fmaf(v.x, drt, drb) + s0;
                v.y = fmaf(v.y, drt, drb) + c12;
                v.z = fmaf(v.z, drt, drb) + c12;
                v.w = fmaf(v.w, drt, drb) + s1;
                __stcs(&og[f4], v);
            }
        }
    }
}

extern "C" void kernel_launch(void* const* d_in, const int* in_sizes, int n_in,
                              void* d_out, int out_size)
{
    const float* x = (const float*)d_in[0];
    const float* z = (const float*)d_in[1];
    const float* y = (const float*)d_in[2];

    // weights -> __constant__ (async D2D memcpys: graph-capturable, no allocs)
    cudaMemcpyToSymbolAsync(cErw, d_in[3],  8 * 4, 0, cudaMemcpyDeviceToDevice, 0);
    cudaMemcpyToSymbolAsync(cErb, d_in[4],  8 * 4, 0, cudaMemcpyDeviceToDevice, 0);
    cudaMemcpyToSymbolAsync(cER,  d_in[5], 64 * 4, 0, cudaMemcpyDeviceToDevice, 0);
    cudaMemcpyToSymbolAsync(cPR,  d_in[6], 64 * 4, 0, cudaMemcpyDeviceToDevice, 0);
    cudaMemcpyToSymbolAsync(cPrb, d_in[7],  8 * 4, 0, cudaMemcpyDeviceToDevice, 0);
    cudaMemcpyToSymbolAsync(cPO,  d_in[8], 64 * 4, 0, cudaMemcpyDeviceToDevice, 0);
    cudaMemcpyToSymbolAsync(cDrw, d_in[9],  8 * 4, 0, cudaMemcpyDeviceToDevice, 0);
    cudaMemcpyToSymbolAsync(cDrb, d_in[10],     4, 0, cudaMemcpyDeviceToDevice, 0);
    cudaMemcpyToSymbolAsync(cDrt, d_in[11],     4, 0, cudaMemcpyDeviceToDevice, 0);

    const long long B = (long long)in_sizes[0] / 40;
    const int threads = 128;                      // 4 warps x 32 elements
    const long long elems_per_block = 128;
    const int blocks = (int)((B + elems_per_block - 1) / elems_per_block);

    fused_gnn_kernel<<<blocks, threads>>>(x, z, y, (float*)d_out, B);
}

// round 11
// speedup vs baseline: 3.2410x; 1.3414x over previous
#include <cuda_runtime.h>

// Fused 3-layer GraphConv, B=524288.
//   A_ENC:  agg[j]  = sum_{i=4j-3..4j+2} x[i mod 40]
//   A_PRED: agg2[j] = z1[j] + w*(z1[j-1] + z1[j+1]),  w = exp(-1/9)
//   A_DEC:  out[4k]=s[k], out[4k+1]=out[4k+2]=s[k]+s[k+1], out[4k+3]=s[k+1]
//           with s[j] = dot(relu(pred(z1)[j]), dec_rel_w)
//
// R10 vs R9 (kernel 170us but bench 185us: 9 memcpy graph nodes = ~15us):
//  - ONE gather kernel packs all weights into contiguous __device__ staging,
//    then ONE cudaMemcpyToSymbolAsync. 9 graph nodes -> 2.
//  - full-block specialization: B % 128 == 0 here, so the hot path drops all
//    bounds predicates (template<bool FULL>); tail path kept generic.
//  - otherwise identical to R9 (constant weights, smem z1 round-trip,
//    volatile LDS/STS anti-hoist, launch_bounds(128,5)).

#define WPRED 0.8948393168143698f

__constant__ __align__(16) float cW[232];
#define C_ER  0     // enc_root_w  [f*8+g]
#define C_PR  64    // pred_rel_w
#define C_PO  128   // pred_root_w
#define C_ERW 192
#define C_ERB 200
#define C_PRB 208
#define C_DRW 216
#define C_DRB 224
#define C_DRT 225

__device__ __align__(16) float gStage[232];

__global__ void gather_weights(const float* __restrict__ erw, const float* __restrict__ erb,
                               const float* __restrict__ er,  const float* __restrict__ pr,
                               const float* __restrict__ prb, const float* __restrict__ po,
                               const float* __restrict__ drw, const float* __restrict__ drb,
                               const float* __restrict__ drt)
{
    const int t = threadIdx.x;
    if (t < 64) {
        gStage[C_ER + t] = er[t];
        gStage[C_PR + t] = pr[t];
        gStage[C_PO + t] = po[t];
    }
    if (t < 8) {
        gStage[C_ERW + t] = erw[t];
        gStage[C_ERB + t] = erb[t];
        gStage[C_PRB + t] = prb[t];
        gStage[C_DRW + t] = drw[t];
    }
    if (t == 0) { gStage[C_DRB] = drb[0]; gStage[C_DRT] = drt[0]; }
}

__device__ __forceinline__ float4 lds128a(unsigned a) {
    float4 r;
    asm volatile("ld.shared.v4.f32 {%0,%1,%2,%3}, [%4];"
                 : "=f"(r.x), "=f"(r.y), "=f"(r.z), "=f"(r.w) : "r"(a));
    return r;
}
__device__ __forceinline__ void sts128a(unsigned a, float4 v) {
    asm volatile("st.shared.v4.f32 [%0], {%1,%2,%3,%4};"
                 :: "r"(a), "f"(v.x), "f"(v.y), "f"(v.z), "f"(v.w));
}
__device__ __forceinline__ unsigned saddr(const void* p) {
    return (unsigned)__cvta_generic_to_shared(p);
}

// predictor node + dec_rel fold, split accumulator chains, constant weights
__device__ __forceinline__ float pred_s(float4 ma, float4 mb, float4 ca, float4 cb,
                                        float4 na, float4 nb)
{
    float4 Aa, Ab;
    Aa.x = fmaf(WPRED, ma.x + na.x, ca.x);
    Aa.y = fmaf(WPRED, ma.y + na.y, ca.y);
    Aa.z = fmaf(WPRED, ma.z + na.z, ca.z);
    Aa.w = fmaf(WPRED, ma.w + na.w, ca.w);
    Ab.x = fmaf(WPRED, mb.x + nb.x, cb.x);
    Ab.y = fmaf(WPRED, mb.y + nb.y, cb.y);
    Ab.z = fmaf(WPRED, mb.z + nb.z, cb.z);
    Ab.w = fmaf(WPRED, mb.w + nb.w, cb.w);
    const float4* pr4 = (const float4*)(cW + C_PR);
    const float4* po4 = (const float4*)(cW + C_PO);
    float sj0 = 0.0f, sj1 = 0.0f;
    #pragma unroll
    for (int f = 0; f < 8; f++) {
        float4 r0 = pr4[f * 2], r1 = pr4[f * 2 + 1];
        float4 o0 = po4[f * 2], o1 = po4[f * 2 + 1];
        float p0 = fmaf(Aa.x, r0.x, fmaf(Aa.y, r0.y, fmaf(Aa.z, r0.z, fmaf(Aa.w, r0.w, cW[C_PRB + f]))));
        float p1 = fmaf(Ab.x, r1.x, fmaf(Ab.y, r1.y, fmaf(Ab.z, r1.z, Ab.w * r1.w)));
        float p2 = fmaf(ca.x, o0.x, fmaf(ca.y, o0.y, fmaf(ca.z, o0.z, ca.w * o0.w)));
        float p3 = fmaf(cb.x, o1.x, fmaf(cb.y, o1.y, fmaf(cb.z, o1.z, cb.w * o1.w)));
        float r = fmaxf((p0 + p1) + (p2 + p3), 0.0f);
        if (f & 1) sj1 = fmaf(r, cW[C_DRW + f], sj1);
        else       sj0 = fmaf(r, cW[C_DRW + f], sj0);
    }
    return sj0 + sj1;
}

template <bool FULL>
__device__ __forceinline__ void body(const float* __restrict__ x,
                                     const float* __restrict__ z,
                                     const float* __restrict__ y,
                                     float* __restrict__ out,
                                     float* buf, int lane, long long e0, int nv)
{
    float* ss = buf;   // alias: reused after z1 dead (32 x stride-11 floats)

    // ===== stage x (coalesced, streaming), rows padded to 44 floats =====
    {
        const float4* xg = (const float4*)(x + e0 * 40);
        const int lim = nv * 10;
        #pragma unroll
        for (int k = 0; k < 10; k++) {
            int f4 = k * 32 + lane;
            if (FULL || f4 < lim) {
                float4 v = __ldcs(&xg[f4]);
                *(float4*)&buf[(f4 / 10) * 44 + (f4 % 10) * 4] = v;
            }
        }
    }
    __syncwarp();

    // agg[j] = (last 3 of float4[j-1]) + (first 3 of float4[j]), rolling window
    float agg[10];
    if (FULL || lane < nv) {
        const unsigned mx = saddr(&buf[lane * 44]);
        float4 vp = lds128a(mx + 9 * 16);
        #pragma unroll
        for (int j = 0; j < 10; j++) {
            float4 v = lds128a(mx + j * 16);
            agg[j] = (vp.y + vp.z) + (vp.w + v.x) + (v.y + v.z);
            vp = v;
        }
    }
    __syncwarp();

    // ===== stage z (coalesced, streaming), rows padded to 84 floats =====
    {
        const float4* zg = (const float4*)(z + e0 * 80);
        const int lim = nv * 20;
        #pragma unroll
        for (int k = 0; k < 20; k++) {
            int f4 = k * 32 + lane;
            if (FULL || f4 < lim) {
                float4 v = __ldcs(&zg[f4]);
                *(float4*)&buf[(f4 / 20) * 84 + (f4 % 20) * 4] = v;
            }
        }
    }
    __syncwarp();

    float s[10];
    if (FULL || lane < nv) {
        const unsigned zr_a = saddr(&buf[lane * 84]);
        const float4* er4 = (const float4*)(cW + C_ER);

        // ---- encoder: z1[j] overwrites z[j] in smem, split chains ----
        #pragma unroll
        for (int j = 0; j < 10; j++) {
            float4 a = lds128a(zr_a + j * 32);
            float4 b = lds128a(zr_a + j * 32 + 16);
            float t[8];
            #pragma unroll
            for (int f = 0; f < 8; f++) {
                float4 w0 = er4[f * 2], w1 = er4[f * 2 + 1];
                float c0 = fmaf(a.x, w0.x, fmaf(a.y, w0.y,
                           fmaf(a.z, w0.z, fmaf(a.w, w0.w,
                           fmaf(agg[j], cW[C_ERW + f], cW[C_ERB + f])))));
                float c1 = fmaf(b.x, w1.x, fmaf(b.y, w1.y, fmaf(b.z, w1.z, b.w * w1.w)));
                t[f] = fmaxf(c0 + c1, 0.0f);
            }
            sts128a(zr_a + j * 32,      make_float4(t[0], t[1], t[2], t[3]));
            sts128a(zr_a + j * 32 + 16, make_float4(t[4], t[5], t[6], t[7]));
        }

        // ---- predictor: explicit rolling window, 1 row load per node ----
        float4 maA = lds128a(zr_a + 0);        // z1[0]
        float4 maB = lds128a(zr_a + 16);
        float4 caA = lds128a(zr_a + 32);       // z1[1]
        float4 caB = lds128a(zr_a + 48);
        #pragma unroll
        for (int j = 1; j <= 8; j++) {
            float4 naA = lds128a(zr_a + (j + 1) * 32);
            float4 naB = lds128a(zr_a + (j + 1) * 32 + 16);
            s[j] = pred_s(maA, maB, caA, caB, naA, naB);
            maA = caA; maB = caB; caA = naA; caB = naB;
        }
        // window: ma=z1[8], ca=z1[9]
        float4 naA = lds128a(zr_a + 0);        // z1[0]
        float4 naB = lds128a(zr_a + 16);
        s[9] = pred_s(maA, maB, caA, caB, naA, naB);
        maA = caA; maB = caB; caA = naA; caB = naB;   // ma=z1[9], ca=z1[0]
        naA = lds128a(zr_a + 32);              // z1[1]
        naB = lds128a(zr_a + 48);
        s[0] = pred_s(maA, maB, caA, caB, naA, naB);
    }
    __syncwarp();   // all pred reads of z1 done -> safe to overwrite via alias

    if (FULL || lane < nv) {
        #pragma unroll
        for (int j = 0; j < 10; j++)
            ss[lane * 11 + j] = s[j];
    }
    __syncwarp();

    // ===== decoder: y streamed from gmem, out written directly, coalesced =====
    {
        const float4* yg = (const float4*)(y + e0 * 40);
        float4* og = (float4*)(out + e0 * 40);
        const float drb = cW[C_DRB], drt = cW[C_DRT];
        const int lim = nv * 10;
        #pragma unroll
        for (int k = 0; k < 10; k++) {
            int f4 = k * 32 + lane;
            if (FULL || f4 < lim) {
                const int e = f4 / 10, c = f4 % 10;
                float4 v = __ldcs(&yg[f4]);
                const float s0 = ss[e * 11 + c];
                const float s1 = ss[e * 11 + ((c + 1) % 10)];
                const float c12 = s0 + s1;
                v.x = fmaf(v.x, drt, drb) + s0;
                v.y = fmaf(v.y, drt, drb) + c12;
                v.z = fmaf(v.z, drt, drb) + c12;
                v.w = fmaf(v.w, drt, drb) + s1;
                __stcs(&og[f4], v);
            }
        }
    }
}

__global__ void __launch_bounds__(128, 5)
fused_gnn_kernel(const float* __restrict__ x,
                 const float* __restrict__ z,
                 const float* __restrict__ y,
                 float* __restrict__ out,
                 long long B)
{
    __shared__ __align__(16) float4 sbuf4[4][672];  // per warp: 32 rows x 84 floats

    const int tid = threadIdx.x;
    const int warp = tid >> 5;
    const int lane = tid & 31;
    const long long e0 = ((long long)blockIdx.x * 4 + warp) * 32;
    if (e0 >= B) return;
    float* buf = (float*)sbuf4[warp];

    if (B - e0 >= 32) {
        body<true>(x, z, y, out, buf, lane, e0, 32);
    } else {
        body<false>(x, z, y, out, buf, lane, e0, (int)(B - e0));
    }
}

extern "C" void kernel_launch(void* const* d_in, const int* in_sizes, int n_in,
                              void* d_out, int out_size)
{
    const float* x = (const float*)d_in[0];
    const float* z = (const float*)d_in[1];
    const float* y = (const float*)d_in[2];

    // 1) pack all weights into contiguous device staging (one kernel node)
    gather_weights<<<1, 64>>>(
        (const float*)d_in[3], (const float*)d_in[4], (const float*)d_in[5],
        (const float*)d_in[6], (const float*)d_in[7], (const float*)d_in[8],
        (const float*)d_in[9], (const float*)d_in[10], (const float*)d_in[11]);

    // 2) one D2D memcpy into __constant__ (graph-capturable)
    void* stage_ptr = nullptr;
    cudaGetSymbolAddress(&stage_ptr, gStage);
    cudaMemcpyToSymbolAsync(cW, stage_ptr, 232 * sizeof(float), 0,
                            cudaMemcpyDeviceToDevice, 0);

    const long long B = (long long)in_sizes[0] / 40;
    const int threads = 128;                      // 4 warps x 32 elements
    const long long elems_per_block = 128;
    const int blocks = (int)((B + elems_per_block - 1) / elems_per_block);

    fused_gnn_kernel<<<blocks, threads>>>(x, z, y, (float*)d_out, B);
}